// round 17
// baseline (speedup 1.0000x reference)
#include <cuda_runtime.h>
#include <cstdint>
#include <cstddef>

#define B_   32
#define T_   256
#define S_   256
#define H_   1024
#define IN3D 1536
#define LDIH 2560
#define AT_OFF 8388608u
#define CP_OFF 10485760u
#define GRID_SEQ 256

// scratch (static device globals; no allocation)
__device__ float g_X  [12582912];   // [8192][1536] row = t*32+b
__device__ float g_pre[33554432];   // [256][32][4096]
__device__ float g_Ka [8388608];    // [32][256][1024]
__device__ float g_Kc [8388608];
__device__ float g_buf[8421376];    // [32][257][1024]
__device__ float g_h  [65536];      // ping-pong [2][32][1024]
__device__ float g_c  [32768];
__device__ float g_cvec[32768];
__device__ float g_sc1[8192];
__device__ float g_sc2[8192];
__device__ unsigned g_flags[GRID_SEQ];  // tree-barrier arrival flags (zero-init)
__device__ unsigned g_rel = 0;          // tree-barrier release word
__device__ unsigned g_genBase = 0;      // persists across launches

__device__ __forceinline__ float sigm(float x){ return 1.f/(1.f + __expf(-x)); }

// flag-tree grid barrier; exact-match generations offset by persistent base
__device__ __forceinline__ void gridbar_tree(unsigned gen)
{
    __syncthreads();
    volatile unsigned* fl = g_flags;
    volatile unsigned* rl = &g_rel;
    if (blockIdx.x == 0) {
        if (threadIdx.x == 0) { __threadfence(); fl[0] = gen; }
        while (fl[threadIdx.x] != gen) __nanosleep(32);
        __threadfence();
        __syncthreads();
        if (threadIdx.x == 0) { *rl = gen; }
    } else {
        if (threadIdx.x == 0) {
            __threadfence();
            fl[blockIdx.x] = gen;
            while (*rl != gen) __nanosleep(32);
            __threadfence();
        }
    }
    __syncthreads();
}

// ---------------- pre-phase kernels (validated) ----------------
__global__ void k_gather(const int* __restrict__ nt, const int* __restrict__ pr,
                         const int* __restrict__ par,
                         const float* __restrict__ nt_emb,
                         const float* __restrict__ rule_emb)
{
    int row = blockIdx.x;            // t*32+b
    int t = row >> 5, b = row & 31;
    int tid = threadIdx.x;           // 128
    const float* s0 = nt_emb   + (size_t)nt [b * T_ + t] * 512;
    const float* s1 = rule_emb + (size_t)pr [b * T_ + t] * 512;
    const float* s2 = rule_emb + (size_t)par[b * T_ + t] * 512;
    float4* dst = (float4*)(g_X + (size_t)row * IN3D);
#pragma unroll
    for (int l = 0; l < 3; ++l) {
        int f = tid + 128 * l, seg = f >> 7, off = f & 127;
        const float* sp = (seg == 0) ? s0 : ((seg == 1) ? s1 : s2);
        dst[f] = ((const float4*)sp)[off];
    }
}

template<int BT>
__global__ __launch_bounds__(256) void sgemm128(
    const float* __restrict__ A, int lda,
    const float* __restrict__ Bm, int ldb,
    float* __restrict__ C, int ldc, int K,
    const float* __restrict__ bias1, const float* __restrict__ bias2)
{
    __shared__ __align__(16) float As[16][132];
    __shared__ __align__(16) float Bs[16][132];
    int tid = threadIdx.x;
    int m0 = blockIdx.y * 128, n0 = blockIdx.x * 128;
    int tm = tid >> 4, tn = tid & 15;
    float acc[8][8];
#pragma unroll
    for (int i = 0; i < 8; ++i)
#pragma unroll
        for (int j = 0; j < 8; ++j) acc[i][j] = 0.f;

    for (int kt = 0; kt < K; kt += 16) {
#pragma unroll
        for (int l = 0; l < 2; ++l) {
            int idx = tid + 256 * l, r = idx >> 2, kv = idx & 3;
            float4 v = *(const float4*)(A + (size_t)(m0 + r) * lda + kt + kv * 4);
            As[kv*4+0][r] = v.x; As[kv*4+1][r] = v.y;
            As[kv*4+2][r] = v.z; As[kv*4+3][r] = v.w;
        }
        if (BT) {
#pragma unroll
            for (int l = 0; l < 2; ++l) {
                int idx = tid + 256 * l, r = idx >> 2, kv = idx & 3;
                float4 v = *(const float4*)(Bm + (size_t)(n0 + r) * ldb + kt + kv * 4);
                Bs[kv*4+0][r] = v.x; Bs[kv*4+1][r] = v.y;
                Bs[kv*4+2][r] = v.z; Bs[kv*4+3][r] = v.w;
            }
        } else {
#pragma unroll
            for (int l = 0; l < 2; ++l) {
                int idx = tid + 256 * l, kr = idx >> 5, nv = idx & 31;
                *(float4*)&Bs[kr][nv * 4] =
                    *(const float4*)(Bm + (size_t)(kt + kr) * ldb + n0 + nv * 4);
            }
        }
        __syncthreads();
#pragma unroll
        for (int kk = 0; kk < 16; ++kk) {
            float4 a0 = *(float4*)&As[kk][tm * 8];
            float4 a1 = *(float4*)&As[kk][tm * 8 + 4];
            float4 b0 = *(float4*)&Bs[kk][tn * 8];
            float4 b1 = *(float4*)&Bs[kk][tn * 8 + 4];
            float av[8] = {a0.x,a0.y,a0.z,a0.w,a1.x,a1.y,a1.z,a1.w};
            float bv[8] = {b0.x,b0.y,b0.z,b0.w,b1.x,b1.y,b1.z,b1.w};
#pragma unroll
            for (int i = 0; i < 8; ++i)
#pragma unroll
                for (int j = 0; j < 8; ++j) acc[i][j] += av[i] * bv[j];
        }
        __syncthreads();
    }
#pragma unroll
    for (int i = 0; i < 8; ++i) {
        int m = m0 + tm * 8 + i;
#pragma unroll
        for (int j = 0; j < 8; ++j) {
            int n = n0 + tn * 8 + j;
            float v = acc[i][j];
            if (bias1) v += bias1[n] + bias2[n];
            C[(size_t)m * ldc + n] = v;
        }
    }
}

// ---------------- persistent sequential kernel phases ----------------

// gates v2: ALL 256 blocks, 16 W-rows each (j = 4q+jj, 4 gates).
// warp -> rows 2w,2w+1; lane -> b. Epilogue regathers via smem tile.
__device__ __forceinline__ void gates_v2(
    float* sh, int* selS,
    const float* __restrict__ Whh, const float* __restrict__ Wih,
    const int* __restrict__ ptv, int i,
    const float* __restrict__ hin, float* __restrict__ hout)
{
    float* xs = sh;           // [32][68]
    float* ws = sh + 2176;    // [16][68]
    float* sa = sh + 3264;    // [16][33]
    int tid = threadIdx.x, warp = tid >> 5, lane = tid & 31;
    int q = blockIdx.x;
    if (tid < 32) {
        int pidx = ptv[tid * T_ + i];
        selS[tid] = (pidx < i) ? (pidx + 1) : 0;
    }
    __syncthreads();
    float a0 = 0.f, a1 = 0.f;
    int bA = tid >> 4, kA = tid & 15, bB = bA + 16;
    int rW = tid >> 4;                                   // 0..15
    int grow = ((rW >> 2) << 10) + q * 4 + (rW & 3);     // g*1024 + j

    float4 x0, x1, w0, nx0, nx1, nw0;
#define GL(c, rx0, rx1, rw) do {                                               \
    int ph = (c) >> 4, kc = ((c) & 15) * 64;                                   \
    const float* Wb = ph ? Wih : Whh;                                          \
    int ldw = ph ? LDIH : 1024;                                                \
    int coff = ph ? IN3D : 0;                                                  \
    const float* xpA = ph ? (g_buf + ((size_t)bA * 257 + selS[bA]) * 1024)     \
                          : (hin + bA * H_);                                   \
    const float* xpB = ph ? (g_buf + ((size_t)bB * 257 + selS[bB]) * 1024)     \
                          : (hin + bB * H_);                                   \
    rx0 = *(const float4*)(xpA + kc + kA * 4);                                 \
    rx1 = *(const float4*)(xpB + kc + kA * 4);                                 \
    rw  = *(const float4*)(Wb + (size_t)grow * ldw + coff + kc + kA * 4);      \
} while (0)
#define GS(rx0, rx1, rw) do {                                                  \
    *(float4*)&xs[bA * 68 + kA * 4] = rx0;                                     \
    *(float4*)&xs[bB * 68 + kA * 4] = rx1;                                     \
    *(float4*)&ws[rW * 68 + kA * 4] = rw;                                      \
} while (0)
    GL(0, x0, x1, w0);
    GS(x0, x1, w0);
    __syncthreads();
    int rA = (warp * 2) * 68, rB = (warp * 2 + 1) * 68;
    for (int c = 0; c < 32; ++c) {
        if (c < 31) GL(c + 1, nx0, nx1, nw0);
#pragma unroll
        for (int kk = 0; kk < 16; ++kk) {
            float4 x  = *(float4*)&xs[lane * 68 + kk * 4];
            float4 wa = *(float4*)&ws[rA + kk * 4];
            float4 wb = *(float4*)&ws[rB + kk * 4];
            a0 += wa.x*x.x + wa.y*x.y + wa.z*x.z + wa.w*x.w;
            a1 += wb.x*x.x + wb.y*x.y + wb.z*x.z + wb.w*x.w;
        }
        __syncthreads();
        if (c < 31) { GS(nx0, nx1, nw0); __syncthreads(); }
    }
#undef GL
#undef GS
    sa[(warp * 2) * 33 + lane] = a0;
    sa[(warp * 2 + 1) * 33 + lane] = a1;
    __syncthreads();
    if (tid < 128) {
        int jj = tid >> 5, b = tid & 31;
        int j = q * 4 + jj;
        size_t pb = ((size_t)i * 32 + b) * 4096;
        float gi = sa[jj * 33 + b]        + g_pre[pb + j];
        float gf = sa[(4 + jj) * 33 + b]  + g_pre[pb + 1024 + j];
        float gg = sa[(8 + jj) * 33 + b]  + g_pre[pb + 2048 + j];
        float go = sa[(12 + jj) * 33 + b] + g_pre[pb + 3072 + j];
        float cn = sigm(gf) * g_c[b * H_ + j] + sigm(gi) * tanhf(gg);
        float hn = sigm(go) * tanhf(cn);
        g_c[b * H_ + j] = cn;
        hout[b * H_ + j] = hn;
        g_buf[((size_t)b * 257 + i + 1) * 1024 + j] = hn;
    }
    __syncthreads();
}

// aout v2: ALL 256 blocks, 4 out-cols each. warps 0..3 compute, all load.
__device__ __forceinline__ void aout_v2(
    float* sh, const float* __restrict__ Wout, float* __restrict__ outbuf,
    int step, const float* __restrict__ hcur)
{
    float* xs = sh;           // [32][68]
    float* ws = sh + 2176;    // [4][68]
    int tid = threadIdx.x, warp = tid >> 5, lane = tid & 31;
    int j0 = blockIdx.x * 4;
    int bA = tid >> 4, kA = tid & 15, bB = bA + 16;
    int rW = tid >> 4;        // valid for tid<64: 0..3
    float acc = 0.f;
    float4 x0, x1, nx0, nx1;
    float4 w0 = make_float4(0.f,0.f,0.f,0.f), nw0 = make_float4(0.f,0.f,0.f,0.f);
#define AL(c, rx0, rx1, rw) do {                                               \
    int ph = (c) >> 4, kc = ((c) & 15) * 64;                                   \
    const float* xb = ph ? hcur : g_cvec;                                      \
    rx0 = *(const float4*)(xb + bA * H_ + kc + kA * 4);                        \
    rx1 = *(const float4*)(xb + bB * H_ + kc + kA * 4);                        \
    if (tid < 64)                                                              \
        rw = *(const float4*)(Wout + (size_t)(j0 + rW) * 2048 + ph * 1024 + kc + kA * 4); \
} while (0)
#define AS(rx0, rx1, rw) do {                                                  \
    *(float4*)&xs[bA * 68 + kA * 4] = rx0;                                     \
    *(float4*)&xs[bB * 68 + kA * 4] = rx1;                                     \
    if (tid < 64) *(float4*)&ws[rW * 68 + kA * 4] = rw;                        \
} while (0)
    AL(0, x0, x1, w0);
    AS(x0, x1, w0);
    __syncthreads();
    for (int c = 0; c < 32; ++c) {
        if (c < 31) AL(c + 1, nx0, nx1, nw0);
        if (warp < 4) {
#pragma unroll
            for (int kk = 0; kk < 16; ++kk) {
                float4 x = *(float4*)&xs[lane * 68 + kk * 4];
                float4 w = *(float4*)&ws[warp * 68 + kk * 4];
                acc += w.x*x.x + w.y*x.y + w.z*x.z + w.w*x.w;
            }
        }
        __syncthreads();
        if (c < 31) { AS(nx0, nx1, nw0); __syncthreads(); }
    }
#undef AL
#undef AS
    if (warp < 4)
        outbuf[((size_t)lane * T_ + step) * H_ + j0 + warp] = tanhf(acc);
}

// scores: 512 warp-units on 256 blocks; q in registers.
// units 0..255: sc1 = h(i).Ka ; 256..511: sc2 = aout(i-1).Kc
__device__ __forceinline__ void phase_scores(
    const int* __restrict__ clen, const float* __restrict__ outbuf,
    const float* __restrict__ hcur, int i, int do1, int do2)
{
    int tid = threadIdx.x, warp = tid >> 5, lane = tid & 31;
    int unit = blockIdx.x * 2 + (warp >> 2);
    int second = (unit >= 256);
    if (second ? !do2 : !do1) return;
    int sub = unit & 255, b = sub >> 3, s0 = (sub & 7) * 32;
    int wIn = warp & 3;

    const float* q;  const float* Km;  float* outp;
    if (!second) { q = hcur + b * H_;                            Km = g_Ka; outp = g_sc1; }
    else         { q = outbuf + ((size_t)b * T_ + (i - 1)) * H_; Km = g_Kc; outp = g_sc2; }
    float4 qv[8];
#pragma unroll
    for (int u = 0; u < 8; ++u) qv[u] = *(const float4*)(q + lane * 4 + u * 128);
    int len = clen[b];
#pragma unroll
    for (int m = 0; m < 8; ++m) {
        int s = s0 + wIn * 8 + m;
        const float* kr = Km + ((size_t)b * S_ + s) * H_;
        float a = 0.f;
#pragma unroll
        for (int u = 0; u < 8; ++u) {
            float4 kv = *(const float4*)(kr + lane * 4 + u * 128);
            a += kv.x*qv[u].x + kv.y*qv[u].y + kv.z*qv[u].z + kv.w*qv[u].w;
        }
#pragma unroll
        for (int o = 16; o > 0; o >>= 1) a += __shfl_xor_sync(0xffffffffu, a, o);
        if (lane == 0) outp[b * S_ + s] = (s < len) ? a : -1e30f;
    }
}

// softmax + cvec slices + score outputs.
// blocks 0..127: (b, hslice) from sc1; 128..159: sc2 -> copy_scores step i-1
__device__ __forceinline__ void phase_cvec(
    float* sh, const float* __restrict__ context, float* __restrict__ outbuf,
    int i, int doA, int doB)
{
    float* ps  = sh;
    float* red = sh + 256;
    int bid = blockIdx.x, tid = threadIdx.x;
    if (bid >= 160) return;
    int typeB = (bid >= 128);
    if (typeB ? !doB : !doA) return;
    int b, slice = 0;
    const float* sc;
    if (!typeB) { b = bid >> 2; slice = bid & 3; sc = g_sc1 + b * S_; }
    else        { b = bid - 128;                 sc = g_sc2 + b * S_; }

    float v = sc[tid];
    red[tid] = v; __syncthreads();
    for (int o = 128; o > 0; o >>= 1) { if (tid < o) red[tid] = fmaxf(red[tid], red[tid+o]); __syncthreads(); }
    float mx = red[0]; __syncthreads();
    float e = __expf(v - mx);
    red[tid] = e; __syncthreads();
    for (int o = 128; o > 0; o >>= 1) { if (tid < o) red[tid] += red[tid+o]; __syncthreads(); }
    float p = e / red[0];
    ps[tid] = p;
    __syncthreads();

    if (typeB) {
        outbuf[CP_OFF + ((size_t)b * T_ + (i - 1)) * S_ + tid] = p;
        return;
    }
    if (slice == 0)
        outbuf[AT_OFF + ((size_t)b * T_ + i) * S_ + tid] = p;

    int h = slice * 256 + tid;
    const float* cp = context + (size_t)b * S_ * H_ + h;
    float acc = 0.f;
#pragma unroll 4
    for (int s = 0; s < 256; ++s) acc += ps[s] * cp[(size_t)s * H_];
    g_cvec[b * H_ + h] = acc;
}

// persistent kernel: whole sequential phase
__global__ __launch_bounds__(256, 2) void k_seq(
    const int* __restrict__ ptv, const int* __restrict__ clen,
    const float* __restrict__ ctx,
    const float* __restrict__ Whh, const float* __restrict__ Wih,
    const float* __restrict__ Wa_out,
    const float* __restrict__ h0, const float* __restrict__ c0,
    float* __restrict__ out)
{
    __shared__ __align__(16) float SH[3792];
    __shared__ int selS[32];
    unsigned bgen = g_genBase;

    // init h, c, buf slot 0
    int idx = blockIdx.x * 256 + threadIdx.x;
    if (idx < 32768) {
        g_h[idx] = h0[idx];
        g_c[idx] = c0[idx];
        int b = idx >> 10, j = idx & 1023;
        g_buf[(size_t)b * 257 * 1024 + j] = 0.f;
    }
    ++bgen; gridbar_tree(bgen);

    for (int i = 0; i < T_; ++i) {
        const float* hin = g_h + (i & 1) * 32768;       // h(i-1)
        float*       ho  = g_h + ((i + 1) & 1) * 32768; // h(i)
        // phase1: gates(i) + aout(i-1), both across all 256 blocks
        gates_v2(SH, selS, Whh, Wih, ptv, i, hin, ho);
        if (i > 0) aout_v2(SH, Wa_out, out, i - 1, hin);
        ++bgen; gridbar_tree(bgen);
        phase_scores(clen, out, ho, i, 1, i > 0);
        ++bgen; gridbar_tree(bgen);
        phase_cvec(SH, ctx, out, i, 1, i > 0);
        ++bgen; gridbar_tree(bgen);
    }
    // epilogue: aout(T-1), then its copy_scores
    aout_v2(SH, Wa_out, out, T_ - 1, g_h + (T_ & 1) * 32768);
    ++bgen; gridbar_tree(bgen);
    phase_scores(clen, out, nullptr, T_, 0, 1);
    ++bgen; gridbar_tree(bgen);
    phase_cvec(SH, ctx, out, T_, 0, 1);

    // persist generation base for the next launch (no one reads it this launch)
    if (blockIdx.x == 0 && threadIdx.x == 0) g_genBase = bgen;
}

extern "C" void kernel_launch(void* const* d_in, const int* in_sizes, int n_in,
                              void* d_out, int out_size)
{
    (void)in_sizes; (void)n_in; (void)out_size;
    const int*   nt     = (const int*)  d_in[0];
    const int*   prevr  = (const int*)  d_in[1];
    const int*   parr   = (const int*)  d_in[2];
    const int*   ptv    = (const int*)  d_in[3];
    const float* ctx    = (const float*)d_in[4];
    const int*   clen   = (const int*)  d_in[5];
    const float* h0     = (const float*)d_in[6];
    const float* c0     = (const float*)d_in[7];
    const float* nt_emb = (const float*)d_in[8];
    const float* r_emb  = (const float*)d_in[9];
    const float* W_ih   = (const float*)d_in[10];
    const float* W_hh   = (const float*)d_in[11];
    const float* b_ih   = (const float*)d_in[12];
    const float* b_hh   = (const float*)d_in[13];
    const float* Wa_in  = (const float*)d_in[14];
    const float* Wa_out = (const float*)d_in[15];
    const float* Wc_in  = (const float*)d_in[16];
    const float* Wc_out = (const float*)d_in[17];
    float* out = (float*)d_out;
    (void)Wc_out;

    float *X, *pre, *Ka, *Kc;
    cudaGetSymbolAddress((void**)&X,   g_X);
    cudaGetSymbolAddress((void**)&pre, g_pre);
    cudaGetSymbolAddress((void**)&Ka,  g_Ka);
    cudaGetSymbolAddress((void**)&Kc,  g_Kc);

    k_gather<<<8192, 128>>>(nt, prevr, parr, nt_emb, r_emb);
    sgemm128<1><<<dim3(32, 64), 256>>>(X, IN3D, W_ih, LDIH, pre, 4096, IN3D, b_ih, b_hh);
    sgemm128<0><<<dim3(8, 64), 256>>>(ctx, 1024, Wa_in, 1024, Ka, 1024, 1024, nullptr, nullptr);
    sgemm128<0><<<dim3(8, 64), 256>>>(ctx, 1024, Wc_in, 1024, Kc, 1024, 1024, nullptr, nullptr);
    k_seq<<<GRID_SEQ, 256>>>(ptv, clen, ctx, W_hh, W_ih, Wa_out, h0, c0, out);
}